// round 13
// baseline (speedup 1.0000x reference)
#include <cuda_runtime.h>
#include <cuda_bf16.h>
#include <math.h>
#include <stdint.h>

// ---------------------------------------------------------------------------
// Problem constants
// ---------------------------------------------------------------------------
#define NV    50000      // nodes
#define NE    800000     // edges (before self loops)
#define ET    (NE + NV)  // edges + self loops
#define F_IN  128
#define H1_   4
#define C1_   64
#define HC1   256        // H1*C1
#define C2_   128
#define NG    32         // graphs
#define NCLS  5

// ---------------------------------------------------------------------------
// Scratch (floats + ints in one __device__ buffer)
// ---------------------------------------------------------------------------
static const size_t OFF_H1    = 0;
static const size_t OFF_OUT1  = OFF_H1   + (size_t)NV * HC1;
static const size_t OFF_H2    = OFF_OUT1 + (size_t)NV * HC1;
static const size_t OFF_OUT2  = OFF_H2   + (size_t)NV * C2_;
static const size_t OFF_ASRC1 = OFF_OUT2 + (size_t)NV * C2_;
static const size_t OFF_ADST1 = OFF_ASRC1 + (size_t)NV * H1_;
static const size_t OFF_ASRC2 = OFF_ADST1 + (size_t)NV * H1_;
static const size_t OFF_ADST2 = OFF_ASRC2 + (size_t)NV;
static const size_t OFF_POOL  = OFF_ADST2 + (size_t)NV;          // zero region start
static const size_t OFF_CNT   = OFF_POOL + (size_t)NG * C2_;
static const size_t ZERO_CNT  = OFF_CNT + NG - OFF_POOL;
// int region
static const size_t OFF_DEG    = OFF_CNT + NG;
static const size_t OFF_ROWPTR = OFF_DEG + NV;
static const size_t OFF_WOFS   = OFF_ROWPTR + NV + 1;   // also scan partials
static const size_t OFF_BSUM   = OFF_WOFS + NV;
static const size_t OFF_COL    = OFF_BSUM + 1024;
static const size_t TOTAL_F    = OFF_COL + ET;

__device__ __align__(128) float g_scratch[TOTAL_F];

// ---------------------------------------------------------------------------
// mma.sync tf32 GEMM with 3xTF32 error compensation (~fp32 accuracy).
// C[M,Ntot] = A[M,K] @ B[K,Ntot]; 128x128 block, BK=32, 8 warps of 64x32.
// ---------------------------------------------------------------------------
__device__ __forceinline__ void mma_tf32(float* c, const uint32_t* a,
                                         const uint32_t* b) {
    asm volatile(
        "mma.sync.aligned.m16n8k8.row.col.f32.tf32.tf32.f32 "
        "{%0,%1,%2,%3}, {%4,%5,%6,%7}, {%8,%9}, {%0,%1,%2,%3};"
        : "+f"(c[0]), "+f"(c[1]), "+f"(c[2]), "+f"(c[3])
        : "r"(a[0]), "r"(a[1]), "r"(a[2]), "r"(a[3]), "r"(b[0]), "r"(b[1]));
}

__device__ __forceinline__ void tf32_split(float x, uint32_t& hi, uint32_t& lo) {
    uint32_t h;
    asm("cvt.rna.tf32.f32 %0, %1;" : "=r"(h) : "f"(x));
    float r = x - __uint_as_float(h);
    uint32_t l;
    asm("cvt.rna.tf32.f32 %0, %1;" : "=r"(l) : "f"(r));
    hi = h; lo = l;
}

#define SPAD 36   // smem row stride in floats: bank = (4*row + col) % 32

__global__ __launch_bounds__(256, 1)
void mma_gemm_kernel(const float* __restrict__ A, const float* __restrict__ B,
                     float* __restrict__ C, int M, int Ntot, int K) {
    __shared__ float As[128 * SPAD];   // As[r][k]  (M-row major, 32 k)
    __shared__ float Bs[128 * SPAD];   // Bs[n][k]  (transposed B tile)
    const int tid  = threadIdx.x;
    const int wid  = tid >> 5, lane = tid & 31;
    const int g    = lane >> 2, tig = lane & 3;
    const int wm   = wid >> 2, wn = wid & 3;     // warp tile (wm*64, wn*32)
    const int m_base = blockIdx.y << 7;
    const int n0     = blockIdx.x << 7;

    float c[4][4][4];
#pragma unroll
    for (int mi = 0; mi < 4; mi++)
#pragma unroll
        for (int ni = 0; ni < 4; ni++)
#pragma unroll
            for (int r = 0; r < 4; r++) c[mi][ni][r] = 0.f;

    for (int k0 = 0; k0 < K; k0 += 32) {
        // stage A tile 128x32 (float4, coalesced)
#pragma unroll
        for (int i = 0; i < 4; i++) {
            int t = tid + i * 256;
            int r = t >> 3, cc = (t & 7) << 2;
            int gr = m_base + r;
            float4 v = make_float4(0.f, 0.f, 0.f, 0.f);
            if (gr < M) v = *(const float4*)(A + (size_t)gr * K + k0 + cc);
            *(float4*)(As + r * SPAD + cc) = v;
        }
        // stage B tile transposed: Bs[n][k]
#pragma unroll
        for (int i = 0; i < 4; i++) {
            int t = tid + i * 256;
            int nn = t & 127, kb = (t >> 7) << 2;
            const float* bp = B + (size_t)(k0 + kb) * Ntot + n0 + nn;
            float4 v;
            v.x = bp[0];
            v.y = bp[(size_t)Ntot];
            v.z = bp[(size_t)Ntot * 2];
            v.w = bp[(size_t)Ntot * 3];
            *(float4*)(Bs + nn * SPAD + kb) = v;
        }
        __syncthreads();

#pragma unroll
        for (int ks = 0; ks < 32; ks += 8) {
            uint32_t ah[4][4], al[4][4];
#pragma unroll
            for (int mi = 0; mi < 4; mi++) {
                int r0 = wm * 64 + mi * 16 + g;
                const float* ap = As + ks + tig;
                tf32_split(ap[r0 * SPAD],           ah[mi][0], al[mi][0]);
                tf32_split(ap[(r0 + 8) * SPAD],     ah[mi][1], al[mi][1]);
                tf32_split(ap[r0 * SPAD + 4],       ah[mi][2], al[mi][2]);
                tf32_split(ap[(r0 + 8) * SPAD + 4], ah[mi][3], al[mi][3]);
            }
            uint32_t bh[4][2], bl[4][2];
#pragma unroll
            for (int ni = 0; ni < 4; ni++) {
                const float* bp = Bs + (wn * 32 + ni * 8 + g) * SPAD + ks;
                tf32_split(bp[tig],     bh[ni][0], bl[ni][0]);
                tf32_split(bp[tig + 4], bh[ni][1], bl[ni][1]);
            }
#pragma unroll
            for (int mi = 0; mi < 4; mi++)
#pragma unroll
                for (int ni = 0; ni < 4; ni++) {
                    mma_tf32(c[mi][ni], al[mi], bh[ni]);
                    mma_tf32(c[mi][ni], ah[mi], bl[ni]);
                    mma_tf32(c[mi][ni], ah[mi], bh[ni]);
                }
        }
        __syncthreads();
    }

    // epilogue: c0 (g, 2t), c1 (g, 2t+1), c2 (g+8, 2t), c3 (g+8, 2t+1)
#pragma unroll
    for (int mi = 0; mi < 4; mi++) {
        int r0 = m_base + wm * 64 + mi * 16 + g;
#pragma unroll
        for (int ni = 0; ni < 4; ni++) {
            int col = n0 + wn * 32 + ni * 8 + tig * 2;
            if (r0 < M)
                *(float2*)(C + (size_t)r0 * Ntot + col) =
                    make_float2(c[mi][ni][0], c[mi][ni][1]);
            if (r0 + 8 < M)
                *(float2*)(C + (size_t)(r0 + 8) * Ntot + col) =
                    make_float2(c[mi][ni][2], c[mi][ni][3]);
        }
    }
}

// ---------------------------------------------------------------------------
// fills
// ---------------------------------------------------------------------------
__global__ void fill_f32(float* p, size_t n) {
    size_t i = (size_t)blockIdx.x * blockDim.x + threadIdx.x;
    if (i < n) p[i] = 0.0f;
}
__global__ void fill_i32(int* p, size_t n, int v) {
    size_t i = (size_t)blockIdx.x * blockDim.x + threadIdx.x;
    if (i < n) p[i] = v;
}

// ---------------------------------------------------------------------------
// CSR build
// ---------------------------------------------------------------------------
__global__ void deg_kernel(const int* __restrict__ edst, int e, int* deg) {
    int i = blockIdx.x * blockDim.x + threadIdx.x;
    if (i < e) atomicAdd(&deg[edst[i]], 1);
}

__device__ __forceinline__ int block_scan_1024(int v, int* wsum) {
    int lane = threadIdx.x & 31, wid = threadIdx.x >> 5;
    int x = v;
#pragma unroll
    for (int o = 1; o < 32; o <<= 1) {
        int t = __shfl_up_sync(0xffffffffu, x, o);
        if (lane >= o) x += t;
    }
    if (lane == 31) wsum[wid] = x;
    __syncthreads();
    if (wid == 0) {
        int w = wsum[lane];
#pragma unroll
        for (int o = 1; o < 32; o <<= 1) {
            int t = __shfl_up_sync(0xffffffffu, w, o);
            if (lane >= o) w += t;
        }
        wsum[lane] = w;
    }
    __syncthreads();
    if (wid > 0) x += wsum[wid - 1];
    return x;
}

__global__ void scan1_kernel(const int* __restrict__ deg, int* partial,
                             int* bsums, int n) {
    __shared__ int wsum[32];
    int i = blockIdx.x * 1024 + threadIdx.x;
    int v = (i < n) ? deg[i] : 0;
    int x = block_scan_1024(v, wsum);
    if (i < n) partial[i] = x;
    if (threadIdx.x == 1023) bsums[blockIdx.x] = x;
}

__global__ void scan2_kernel(int* bsums, int nb) {
    __shared__ int wsum[32];
    int v = (threadIdx.x < nb) ? bsums[threadIdx.x] : 0;
    int x = block_scan_1024(v, wsum);
    if (threadIdx.x < nb) bsums[threadIdx.x] = x;
}

__global__ void scan3_kernel(const int* __restrict__ deg,
                             int* __restrict__ partial,
                             const int* __restrict__ bscan,
                             int* __restrict__ rowptr,
                             int* __restrict__ wofs, int n) {
    int i = blockIdx.x * 1024 + threadIdx.x;
    if (i >= n) return;
    int off = blockIdx.x > 0 ? bscan[blockIdx.x - 1] : 0;
    int inc = partial[i] + off;
    rowptr[i + 1] = inc;
    wofs[i] = inc - deg[i];
    if (i == 0) rowptr[0] = 0;
}

__global__ void scatter_kernel(const int* __restrict__ esrc,
                               const int* __restrict__ edst, int e, int et,
                               int* wofs, int* col) {
    int i = blockIdx.x * blockDim.x + threadIdx.x;
    if (i >= et) return;
    int s, d;
    if (i < e) { s = esrc[i]; d = edst[i]; }
    else       { s = d = i - e; }
    int pos = atomicAdd(&wofs[d], 1);
    col[pos] = s;
}

// ---------------------------------------------------------------------------
// attention scores: one warp per node, vectorized
// ---------------------------------------------------------------------------
template<int H, int C>
__global__ void attscore_kernel(const float* __restrict__ h,
                                const float* __restrict__ att_s,
                                const float* __restrict__ att_d,
                                float* __restrict__ asrc,
                                float* __restrict__ adst, int n) {
    constexpr int HC  = H * C;
    constexpr int PER = HC / 32;
    constexpr int SEG = C / PER;
    int node = (int)(((size_t)blockIdx.x * blockDim.x + threadIdx.x) >> 5);
    int lane = threadIdx.x & 31;
    if (node >= n) return;
    const float* row = h + (size_t)node * HC + lane * PER;
    const float* as  = att_s + lane * PER;
    const float* ad  = att_d + lane * PER;
    float ss = 0.f, sd = 0.f;
#pragma unroll
    for (int k = 0; k < PER; k += 4) {
        float4 hv = *(const float4*)(row + k);
        float4 av = *(const float4*)(as + k);
        float4 dv = *(const float4*)(ad + k);
        ss += hv.x * av.x + hv.y * av.y + hv.z * av.z + hv.w * av.w;
        sd += hv.x * dv.x + hv.y * dv.y + hv.z * dv.z + hv.w * dv.w;
    }
#pragma unroll
    for (int o = SEG / 2; o; o >>= 1) {
        ss += __shfl_down_sync(0xffffffffu, ss, o, SEG);
        sd += __shfl_down_sync(0xffffffffu, sd, o, SEG);
    }
    if ((lane % SEG) == 0) {
        int hh = lane / SEG;
        asrc[node * H + hh] = ss;
        adst[node * H + hh] = sd;
    }
}

// ---------------------------------------------------------------------------
// fused GAT layer: per-dst-node block (no max pass; logits bounded).
// ---------------------------------------------------------------------------
template<int H, int C>
__global__ void gat_fused_kernel(const int* __restrict__ rowptr,
                                 const int* __restrict__ colidx,
                                 const float* __restrict__ h,
                                 const float* __restrict__ asrc,
                                 const float* __restrict__ adst,
                                 const float* __restrict__ bias,
                                 float* __restrict__ out) {
    constexpr int HC = H * C;
    constexpr int CHUNK = 32;
    const int node = blockIdx.x;
    const int tid = threadIdx.x;
    __shared__ float s_adst[H];
    __shared__ float s_den[H];
    __shared__ float sw[CHUNK * H];
    __shared__ int   sidx[CHUNK];

    const int row0 = rowptr[node];
    const int deg  = rowptr[node + 1] - row0;
    if (tid < H) {
        s_adst[tid] = adst[node * H + tid];
        s_den[tid]  = 0.f;
    }
    __syncthreads();

    const int myh = tid / C;
    float acc = 0.f;

    // chunked weight compute + register aggregation
    for (int base = 0; base < deg; base += CHUNK) {
        int m = min(CHUNK, deg - base);
        if (tid < m * H) {
            int eidx = tid / H, hh = tid % H;
            int s = colidx[row0 + base + eidx];
            if (hh == 0) sidx[eidx] = s;
            float a = asrc[s * H + hh] + s_adst[hh];
            a = a > 0.f ? a : 0.2f * a;
            float w = __expf(a);
            sw[eidx * H + hh] = w;
            atomicAdd(&s_den[hh], w);
        }
        __syncthreads();
#pragma unroll 8
        for (int j = 0; j < m; j++)
            acc = fmaf(sw[j * H + myh], h[(size_t)sidx[j] * HC + tid], acc);
        __syncthreads();
    }

    float v = acc / (s_den[myh] + 1e-16f) + bias[tid];
    v = v > 0.f ? v : expm1f(v);
    out[(size_t)node * HC + tid] = v;
}

// ---------------------------------------------------------------------------
// pooling: counts + run-accumulated sums over sorted batch (few atomics)
// ---------------------------------------------------------------------------
__global__ void count_kernel(const int* __restrict__ batch, int n,
                             float* __restrict__ cnt) {
    __shared__ int sc[NG];
    if (threadIdx.x < NG) sc[threadIdx.x] = 0;
    __syncthreads();
    int i = blockIdx.x * blockDim.x + threadIdx.x;
    if (i < n) atomicAdd(&sc[batch[i]], 1);
    __syncthreads();
    if (threadIdx.x < NG && sc[threadIdx.x])
        atomicAdd(&cnt[threadIdx.x], (float)sc[threadIdx.x]);
}

#define POOL_NODES_PER_BLOCK 512
__global__ void pool_sum_kernel(const float* __restrict__ h,
                                const int* __restrict__ batch, int n,
                                float* __restrict__ pool) {
    int c = threadIdx.x;  // 128 threads = channels
    int start = blockIdx.x * POOL_NODES_PER_BLOCK;
    int end = start + POOL_NODES_PER_BLOCK;
    if (end > n) end = n;
    float acc = 0.f;
    int cur = -1;
    for (int i = start; i < end; i++) {
        int g = batch[i];
        if (g != cur) {
            if (cur >= 0) atomicAdd(&pool[cur * C2_ + c], acc);
            acc = 0.f;
            cur = g;
        }
        acc += h[(size_t)i * C2_ + c];
    }
    if (cur >= 0) atomicAdd(&pool[cur * C2_ + c], acc);
}

__global__ void final_kernel(const float* __restrict__ pool,
                             const float* __restrict__ cnt,
                             const float* __restrict__ w,
                             const float* __restrict__ b,
                             float* __restrict__ out) {
    int t = threadIdx.x;
    if (t >= NG * NCLS) return;
    int g = t / NCLS, k = t % NCLS;
    float s = 0.f;
#pragma unroll 8
    for (int c = 0; c < C2_; c++) s += pool[g * C2_ + c] * w[c * NCLS + k];
    float n = cnt[g];
    out[t] = s / (n > 1.f ? n : 1.f) + b[k];
}

// ---------------------------------------------------------------------------
// launch
// ---------------------------------------------------------------------------
extern "C" void kernel_launch(void* const* d_in, const int* in_sizes, int n_in,
                              void* d_out, int out_size) {
    const float* x   = (const float*)d_in[0];
    const int*   ei  = (const int*)d_in[1];   // int32 (JAX x64 disabled)
    const int*   bat = (const int*)d_in[2];
    const float* W1  = (const float*)d_in[3];
    const float* as1 = (const float*)d_in[4];
    const float* ad1 = (const float*)d_in[5];
    const float* b1  = (const float*)d_in[6];
    const float* W2  = (const float*)d_in[7];
    const float* as2 = (const float*)d_in[8];
    const float* ad2 = (const float*)d_in[9];
    const float* b2  = (const float*)d_in[10];
    const float* lw  = (const float*)d_in[11];
    const float* lb  = (const float*)d_in[12];
    float* out = (float*)d_out;

    const int n  = in_sizes[0] / F_IN;   // 50000
    const int e  = in_sizes[1] / 2;      // 800000
    const int et = e + n;
    const int nb = (n + 1023) / 1024;    // scan blocks
    const int* esrc = ei;
    const int* edst = ei + e;

    float* base;
    cudaGetSymbolAddress((void**)&base, g_scratch);
    float* h1    = base + OFF_H1;
    float* out1  = base + OFF_OUT1;
    float* h2    = base + OFF_H2;
    float* out2  = base + OFF_OUT2;
    float* asrc1 = base + OFF_ASRC1;
    float* adst1 = base + OFF_ADST1;
    float* asrc2 = base + OFF_ASRC2;
    float* adst2 = base + OFF_ADST2;
    float* pool  = base + OFF_POOL;
    float* cnt   = base + OFF_CNT;
    int* deg     = (int*)(base + OFF_DEG);
    int* rowptr  = (int*)(base + OFF_ROWPTR);
    int* wofs    = (int*)(base + OFF_WOFS);
    int* bsum    = (int*)(base + OFF_BSUM);
    int* col     = (int*)(base + OFF_COL);

    // one-time side stream + events (created on first, non-captured call)
    static cudaStream_t s2 = nullptr;
    static cudaEvent_t evFork = nullptr, evJoin = nullptr;
    if (s2 == nullptr) {
        cudaStreamCreateWithFlags(&s2, cudaStreamNonBlocking);
        cudaEventCreateWithFlags(&evFork, cudaEventDisableTiming);
        cudaEventCreateWithFlags(&evJoin, cudaEventDisableTiming);
    }

    // --- fork: CSR build + pool zero + counts on s2 -------------------------
    cudaEventRecord(evFork, 0);
    cudaStreamWaitEvent(s2, evFork, 0);

    fill_f32<<<(unsigned)((ZERO_CNT + 255) / 256), 256, 0, s2>>>(pool, ZERO_CNT);
    fill_i32<<<(n + 255) / 256, 256, 0, s2>>>(deg, n, 1);       // self loop
    deg_kernel<<<(e + 511) / 512, 512, 0, s2>>>(edst, e, deg);
    scan1_kernel<<<nb, 1024, 0, s2>>>(deg, wofs, bsum, n);      // partials in wofs
    scan2_kernel<<<1, 1024, 0, s2>>>(bsum, nb);
    scan3_kernel<<<nb, 1024, 0, s2>>>(deg, wofs, bsum, rowptr, wofs, n);
    scatter_kernel<<<(et + 511) / 512, 512, 0, s2>>>(esrc, edst, e, et, wofs, col);
    count_kernel<<<(n + 255) / 256, 256, 0, s2>>>(bat, n, cnt);

    cudaEventRecord(evJoin, s2);

    // --- main stream: GEMM1 (3xTF32 tensor core) + attscore1 ------------------
    {
        dim3 grid(HC1 / 128, (n + 127) / 128);
        mma_gemm_kernel<<<grid, 256>>>(x, W1, h1, n, HC1, F_IN);
    }
    attscore_kernel<H1_, C1_><<<(n * 32 + 255) / 256, 256>>>(h1, as1, ad1, asrc1, adst1, n);

    // --- join, then fused layer 1 -------------------------------------------
    cudaStreamWaitEvent(0, evJoin, 0);
    gat_fused_kernel<H1_, C1_><<<n, HC1>>>(rowptr, col, h1, asrc1, adst1, b1, out1);

    // --- layer 2 -------------------------------------------------------------
    {
        dim3 grid(C2_ / 128, (n + 127) / 128);
        mma_gemm_kernel<<<grid, 256>>>(out1, W2, h2, n, C2_, HC1);
    }
    attscore_kernel<1, C2_><<<(n * 32 + 255) / 256, 256>>>(h2, as2, ad2, asrc2, adst2, n);
    gat_fused_kernel<1, C2_><<<n, C2_>>>(rowptr, col, h2, asrc2, adst2, b2, out2);

    // --- pooling + head ------------------------------------------------------
    pool_sum_kernel<<<(n + POOL_NODES_PER_BLOCK - 1) / POOL_NODES_PER_BLOCK, C2_>>>(out2, bat, n, pool);
    final_kernel<<<1, NG * NCLS>>>(pool, cnt, lw, lb, out);
}

// round 14
// speedup vs baseline: 1.3637x; 1.3637x over previous
#include <cuda_runtime.h>
#include <cuda_bf16.h>
#include <math.h>
#include <stdint.h>

// ---------------------------------------------------------------------------
// Problem constants
// ---------------------------------------------------------------------------
#define NV    50000      // nodes
#define NE    800000     // edges (before self loops)
#define ET    (NE + NV)  // edges + self loops
#define F_IN  128
#define H1_   4
#define C1_   64
#define HC1   256        // H1*C1
#define C2_   128
#define NG    32         // graphs
#define NCLS  5

// ---------------------------------------------------------------------------
// Scratch (floats + ints in one __device__ buffer)
// ---------------------------------------------------------------------------
static const size_t OFF_H1    = 0;
static const size_t OFF_OUT1  = OFF_H1   + (size_t)NV * HC1;
static const size_t OFF_H2    = OFF_OUT1 + (size_t)NV * HC1;
static const size_t OFF_ASRC1 = OFF_H2   + (size_t)NV * C2_;
static const size_t OFF_ADST1 = OFF_ASRC1 + (size_t)NV * H1_;
static const size_t OFF_ASRC2 = OFF_ADST1 + (size_t)NV * H1_;
static const size_t OFF_ADST2 = OFF_ASRC2 + (size_t)NV;
static const size_t OFF_POOL  = OFF_ADST2 + (size_t)NV;          // zero region start
static const size_t OFF_CNT   = OFF_POOL + (size_t)NG * C2_;
static const size_t ZERO_CNT  = OFF_CNT + NG - OFF_POOL;
// int region
static const size_t OFF_DEG    = OFF_CNT + NG;
static const size_t OFF_ROWPTR = OFF_DEG + NV;
static const size_t OFF_WOFS   = OFF_ROWPTR + NV + 1;   // also scan partials
static const size_t OFF_BSUM   = OFF_WOFS + NV;
static const size_t OFF_COL    = OFF_BSUM + 1024;
static const size_t TOTAL_F    = OFF_COL + ET;

__device__ __align__(128) float g_scratch[TOTAL_F];

// ---------------------------------------------------------------------------
// helpers
// ---------------------------------------------------------------------------
__device__ __forceinline__ void red_add_v4(float* addr, float4 v) {
    asm volatile("red.global.add.v4.f32 [%0], {%1, %2, %3, %4};"
                 :: "l"(addr), "f"(v.x), "f"(v.y), "f"(v.z), "f"(v.w)
                 : "memory");
}

// ---------------------------------------------------------------------------
// mma.sync tf32 GEMM with 3xTF32 error compensation (~fp32 accuracy).
// C[M,Ntot] = A[M,K] @ B[K,Ntot]; 128x128 block, BK=32, 8 warps of 64x32.
// ---------------------------------------------------------------------------
__device__ __forceinline__ void mma_tf32(float* c, const uint32_t* a,
                                         const uint32_t* b) {
    asm volatile(
        "mma.sync.aligned.m16n8k8.row.col.f32.tf32.tf32.f32 "
        "{%0,%1,%2,%3}, {%4,%5,%6,%7}, {%8,%9}, {%0,%1,%2,%3};"
        : "+f"(c[0]), "+f"(c[1]), "+f"(c[2]), "+f"(c[3])
        : "r"(a[0]), "r"(a[1]), "r"(a[2]), "r"(a[3]), "r"(b[0]), "r"(b[1]));
}

__device__ __forceinline__ void tf32_split(float x, uint32_t& hi, uint32_t& lo) {
    uint32_t h;
    asm("cvt.rna.tf32.f32 %0, %1;" : "=r"(h) : "f"(x));
    float r = x - __uint_as_float(h);
    uint32_t l;
    asm("cvt.rna.tf32.f32 %0, %1;" : "=r"(l) : "f"(r));
    hi = h; lo = l;
}

#define SPAD 36   // smem row stride in floats: bank = (4*row + col) % 32

__global__ __launch_bounds__(256, 1)
void mma_gemm_kernel(const float* __restrict__ A, const float* __restrict__ B,
                     float* __restrict__ C, int M, int Ntot, int K) {
    __shared__ float As[128 * SPAD];   // As[r][k]  (M-row major, 32 k)
    __shared__ float Bs[128 * SPAD];   // Bs[n][k]  (transposed B tile)
    const int tid  = threadIdx.x;
    const int wid  = tid >> 5, lane = tid & 31;
    const int g    = lane >> 2, tig = lane & 3;
    const int wm   = wid >> 2, wn = wid & 3;     // warp tile (wm*64, wn*32)
    const int m_base = blockIdx.y << 7;
    const int n0     = blockIdx.x << 7;

    float c[4][4][4];
#pragma unroll
    for (int mi = 0; mi < 4; mi++)
#pragma unroll
        for (int ni = 0; ni < 4; ni++)
#pragma unroll
            for (int r = 0; r < 4; r++) c[mi][ni][r] = 0.f;

    for (int k0 = 0; k0 < K; k0 += 32) {
        // stage A tile 128x32 (float4, coalesced)
#pragma unroll
        for (int i = 0; i < 4; i++) {
            int t = tid + i * 256;
            int r = t >> 3, cc = (t & 7) << 2;
            int gr = m_base + r;
            float4 v = make_float4(0.f, 0.f, 0.f, 0.f);
            if (gr < M) v = *(const float4*)(A + (size_t)gr * K + k0 + cc);
            *(float4*)(As + r * SPAD + cc) = v;
        }
        // stage B tile transposed: Bs[n][k]
#pragma unroll
        for (int i = 0; i < 4; i++) {
            int t = tid + i * 256;
            int nn = t & 127, kb = (t >> 7) << 2;
            const float* bp = B + (size_t)(k0 + kb) * Ntot + n0 + nn;
            float4 v;
            v.x = bp[0];
            v.y = bp[(size_t)Ntot];
            v.z = bp[(size_t)Ntot * 2];
            v.w = bp[(size_t)Ntot * 3];
            *(float4*)(Bs + nn * SPAD + kb) = v;
        }
        __syncthreads();

#pragma unroll
        for (int ks = 0; ks < 32; ks += 8) {
            uint32_t ah[4][4], al[4][4];
#pragma unroll
            for (int mi = 0; mi < 4; mi++) {
                int r0 = wm * 64 + mi * 16 + g;
                const float* ap = As + ks + tig;
                tf32_split(ap[r0 * SPAD],           ah[mi][0], al[mi][0]);
                tf32_split(ap[(r0 + 8) * SPAD],     ah[mi][1], al[mi][1]);
                tf32_split(ap[r0 * SPAD + 4],       ah[mi][2], al[mi][2]);
                tf32_split(ap[(r0 + 8) * SPAD + 4], ah[mi][3], al[mi][3]);
            }
            uint32_t bh[4][2], bl[4][2];
#pragma unroll
            for (int ni = 0; ni < 4; ni++) {
                const float* bp = Bs + (wn * 32 + ni * 8 + g) * SPAD + ks;
                tf32_split(bp[tig],     bh[ni][0], bl[ni][0]);
                tf32_split(bp[tig + 4], bh[ni][1], bl[ni][1]);
            }
#pragma unroll
            for (int mi = 0; mi < 4; mi++)
#pragma unroll
                for (int ni = 0; ni < 4; ni++) {
                    mma_tf32(c[mi][ni], al[mi], bh[ni]);
                    mma_tf32(c[mi][ni], ah[mi], bl[ni]);
                    mma_tf32(c[mi][ni], ah[mi], bh[ni]);
                }
        }
        __syncthreads();
    }

    // epilogue: c0 (g, 2t), c1 (g, 2t+1), c2 (g+8, 2t), c3 (g+8, 2t+1)
#pragma unroll
    for (int mi = 0; mi < 4; mi++) {
        int r0 = m_base + wm * 64 + mi * 16 + g;
#pragma unroll
        for (int ni = 0; ni < 4; ni++) {
            int col = n0 + wn * 32 + ni * 8 + tig * 2;
            if (r0 < M)
                *(float2*)(C + (size_t)r0 * Ntot + col) =
                    make_float2(c[mi][ni][0], c[mi][ni][1]);
            if (r0 + 8 < M)
                *(float2*)(C + (size_t)(r0 + 8) * Ntot + col) =
                    make_float2(c[mi][ni][2], c[mi][ni][3]);
        }
    }
}

// ---------------------------------------------------------------------------
// fills
// ---------------------------------------------------------------------------
__global__ void fill_f32(float* p, size_t n) {
    size_t i = (size_t)blockIdx.x * blockDim.x + threadIdx.x;
    if (i < n) p[i] = 0.0f;
}
__global__ void fill_i32(int* p, size_t n, int v) {
    size_t i = (size_t)blockIdx.x * blockDim.x + threadIdx.x;
    if (i < n) p[i] = v;
}

// ---------------------------------------------------------------------------
// CSR build
// ---------------------------------------------------------------------------
__global__ void deg_kernel(const int* __restrict__ edst, int e, int* deg) {
    int i = blockIdx.x * blockDim.x + threadIdx.x;
    if (i < e) atomicAdd(&deg[edst[i]], 1);
}

__device__ __forceinline__ int block_scan_1024(int v, int* wsum) {
    int lane = threadIdx.x & 31, wid = threadIdx.x >> 5;
    int x = v;
#pragma unroll
    for (int o = 1; o < 32; o <<= 1) {
        int t = __shfl_up_sync(0xffffffffu, x, o);
        if (lane >= o) x += t;
    }
    if (lane == 31) wsum[wid] = x;
    __syncthreads();
    if (wid == 0) {
        int w = wsum[lane];
#pragma unroll
        for (int o = 1; o < 32; o <<= 1) {
            int t = __shfl_up_sync(0xffffffffu, w, o);
            if (lane >= o) w += t;
        }
        wsum[lane] = w;
    }
    __syncthreads();
    if (wid > 0) x += wsum[wid - 1];
    return x;
}

__global__ void scan1_kernel(const int* __restrict__ deg, int* partial,
                             int* bsums, int n) {
    __shared__ int wsum[32];
    int i = blockIdx.x * 1024 + threadIdx.x;
    int v = (i < n) ? deg[i] : 0;
    int x = block_scan_1024(v, wsum);
    if (i < n) partial[i] = x;
    if (threadIdx.x == 1023) bsums[blockIdx.x] = x;
}

__global__ void scan2_kernel(int* bsums, int nb) {
    __shared__ int wsum[32];
    int v = (threadIdx.x < nb) ? bsums[threadIdx.x] : 0;
    int x = block_scan_1024(v, wsum);
    if (threadIdx.x < nb) bsums[threadIdx.x] = x;
}

__global__ void scan3_kernel(const int* __restrict__ deg,
                             int* __restrict__ partial,
                             const int* __restrict__ bscan,
                             int* __restrict__ rowptr,
                             int* __restrict__ wofs, int n) {
    int i = blockIdx.x * 1024 + threadIdx.x;
    if (i >= n) return;
    int off = blockIdx.x > 0 ? bscan[blockIdx.x - 1] : 0;
    int inc = partial[i] + off;
    rowptr[i + 1] = inc;
    wofs[i] = inc - deg[i];
    if (i == 0) rowptr[0] = 0;
}

__global__ void scatter_kernel(const int* __restrict__ esrc,
                               const int* __restrict__ edst, int e, int et,
                               int* wofs, int* col) {
    int i = blockIdx.x * blockDim.x + threadIdx.x;
    if (i >= et) return;
    int s, d;
    if (i < e) { s = esrc[i]; d = edst[i]; }
    else       { s = d = i - e; }
    int pos = atomicAdd(&wofs[d], 1);
    col[pos] = s;
}

// ---------------------------------------------------------------------------
// attention scores: one warp per node, vectorized
// ---------------------------------------------------------------------------
template<int H, int C>
__global__ void attscore_kernel(const float* __restrict__ h,
                                const float* __restrict__ att_s,
                                const float* __restrict__ att_d,
                                float* __restrict__ asrc,
                                float* __restrict__ adst, int n) {
    constexpr int HC  = H * C;
    constexpr int PER = HC / 32;
    constexpr int SEG = C / PER;
    int node = (int)(((size_t)blockIdx.x * blockDim.x + threadIdx.x) >> 5);
    int lane = threadIdx.x & 31;
    if (node >= n) return;
    const float* row = h + (size_t)node * HC + lane * PER;
    const float* as  = att_s + lane * PER;
    const float* ad  = att_d + lane * PER;
    float ss = 0.f, sd = 0.f;
#pragma unroll
    for (int k = 0; k < PER; k += 4) {
        float4 hv = *(const float4*)(row + k);
        float4 av = *(const float4*)(as + k);
        float4 dv = *(const float4*)(ad + k);
        ss += hv.x * av.x + hv.y * av.y + hv.z * av.z + hv.w * av.w;
        sd += hv.x * dv.x + hv.y * dv.y + hv.z * dv.z + hv.w * dv.w;
    }
#pragma unroll
    for (int o = SEG / 2; o; o >>= 1) {
        ss += __shfl_down_sync(0xffffffffu, ss, o, SEG);
        sd += __shfl_down_sync(0xffffffffu, sd, o, SEG);
    }
    if ((lane % SEG) == 0) {
        int hh = lane / SEG;
        asrc[node * H + hh] = ss;
        adst[node * H + hh] = sd;
    }
}

// ---------------------------------------------------------------------------
// warp-per-node fused GAT layer. No block barriers: per-warp smem staging,
// register den with one final warp reduction (unnormalized-weight trick).
// blockDim = 256 (8 warps = 8 nodes per block).
// ---------------------------------------------------------------------------
template<int H, int C, bool POOL>
__global__ __launch_bounds__(256)
void gat_warp_kernel(const int* __restrict__ rowptr,
                     const int* __restrict__ colidx,
                     const float* __restrict__ h,
                     const float* __restrict__ asrc,
                     const float* __restrict__ adst,
                     const float* __restrict__ bias,
                     float* __restrict__ out,
                     const int* __restrict__ batch,
                     float* __restrict__ pool, int n) {
    constexpr int HC  = H * C;
    constexpr int PER = HC / 32;   // floats per lane (8 for L1, 4 for L2)
    constexpr int NF4 = PER / 4;   // float4s per lane (2 or 1)
    const int wid  = threadIdx.x >> 5;
    const int lane = threadIdx.x & 31;
    const int node = blockIdx.x * 8 + wid;

    __shared__ float ssw[8][32 * H];
    __shared__ int   ssx[8][32];

    if (node >= n) return;

    const int row0 = rowptr[node];
    const int deg  = rowptr[node + 1] - row0;
    const int myh  = (lane * PER) / C;

    float ad[H], den[H];
#pragma unroll
    for (int hh = 0; hh < H; hh++) {
        ad[hh]  = adst[node * H + hh];
        den[hh] = 0.f;
    }
    float4 acc[NF4];
#pragma unroll
    for (int q = 0; q < NF4; q++) acc[q] = make_float4(0.f, 0.f, 0.f, 0.f);

    for (int base = 0; base < deg; base += 32) {
        int m = min(32, deg - base);
        if (lane < m) {
            int s = colidx[row0 + base + lane];
            ssx[wid][lane] = s;
#pragma unroll
            for (int hh = 0; hh < H; hh++) {
                float a = asrc[s * H + hh] + ad[hh];
                a = a > 0.f ? a : 0.2f * a;
                float w = __expf(a);
                ssw[wid][lane * H + hh] = w;
                den[hh] += w;
            }
        }
        __syncwarp();
#pragma unroll 4
        for (int j = 0; j < m; j++) {
            float w = ssw[wid][j * H + myh];
            const float4* hp =
                (const float4*)(h + (size_t)ssx[wid][j] * HC + lane * PER);
#pragma unroll
            for (int q = 0; q < NF4; q++) {
                float4 hv = hp[q];
                acc[q].x = fmaf(w, hv.x, acc[q].x);
                acc[q].y = fmaf(w, hv.y, acc[q].y);
                acc[q].z = fmaf(w, hv.z, acc[q].z);
                acc[q].w = fmaf(w, hv.w, acc[q].w);
            }
        }
        __syncwarp();
    }

    // reduce den across lanes (all lanes get the sums)
#pragma unroll
    for (int hh = 0; hh < H; hh++)
#pragma unroll
        for (int o = 16; o; o >>= 1)
            den[hh] += __shfl_xor_sync(0xffffffffu, den[hh], o);

    const float rden = 1.0f / (den[myh] + 1e-16f);
#pragma unroll
    for (int q = 0; q < NF4; q++) {
        int c0 = lane * PER + q * 4;
        float4 bv = *(const float4*)(bias + c0);
        float4 v;
        v.x = acc[q].x * rden + bv.x;
        v.y = acc[q].y * rden + bv.y;
        v.z = acc[q].z * rden + bv.z;
        v.w = acc[q].w * rden + bv.w;
        v.x = v.x > 0.f ? v.x : expm1f(v.x);
        v.y = v.y > 0.f ? v.y : expm1f(v.y);
        v.z = v.z > 0.f ? v.z : expm1f(v.z);
        v.w = v.w > 0.f ? v.w : expm1f(v.w);
        if (POOL) {
            red_add_v4(pool + (size_t)batch[node] * HC + c0, v);
        } else {
            *(float4*)(out + (size_t)node * HC + c0) = v;
        }
    }
}

// ---------------------------------------------------------------------------
// graph-size counts + linear head
// ---------------------------------------------------------------------------
__global__ void count_kernel(const int* __restrict__ batch, int n,
                             float* __restrict__ cnt) {
    __shared__ int sc[NG];
    if (threadIdx.x < NG) sc[threadIdx.x] = 0;
    __syncthreads();
    int i = blockIdx.x * blockDim.x + threadIdx.x;
    if (i < n) atomicAdd(&sc[batch[i]], 1);
    __syncthreads();
    if (threadIdx.x < NG && sc[threadIdx.x])
        atomicAdd(&cnt[threadIdx.x], (float)sc[threadIdx.x]);
}

__global__ void final_kernel(const float* __restrict__ pool,
                             const float* __restrict__ cnt,
                             const float* __restrict__ w,
                             const float* __restrict__ b,
                             float* __restrict__ out) {
    int t = threadIdx.x;
    if (t >= NG * NCLS) return;
    int g = t / NCLS, k = t % NCLS;
    float s = 0.f;
#pragma unroll 8
    for (int c = 0; c < C2_; c++) s += pool[g * C2_ + c] * w[c * NCLS + k];
    float n = cnt[g];
    out[t] = s / (n > 1.f ? n : 1.f) + b[k];
}

// ---------------------------------------------------------------------------
// launch
// ---------------------------------------------------------------------------
extern "C" void kernel_launch(void* const* d_in, const int* in_sizes, int n_in,
                              void* d_out, int out_size) {
    const float* x   = (const float*)d_in[0];
    const int*   ei  = (const int*)d_in[1];   // int32 (JAX x64 disabled)
    const int*   bat = (const int*)d_in[2];
    const float* W1  = (const float*)d_in[3];
    const float* as1 = (const float*)d_in[4];
    const float* ad1 = (const float*)d_in[5];
    const float* b1  = (const float*)d_in[6];
    const float* W2  = (const float*)d_in[7];
    const float* as2 = (const float*)d_in[8];
    const float* ad2 = (const float*)d_in[9];
    const float* b2  = (const float*)d_in[10];
    const float* lw  = (const float*)d_in[11];
    const float* lb  = (const float*)d_in[12];
    float* out = (float*)d_out;

    const int n  = in_sizes[0] / F_IN;   // 50000
    const int e  = in_sizes[1] / 2;      // 800000
    const int et = e + n;
    const int nb = (n + 1023) / 1024;    // scan blocks
    const int* esrc = ei;
    const int* edst = ei + e;

    float* base;
    cudaGetSymbolAddress((void**)&base, g_scratch);
    float* h1    = base + OFF_H1;
    float* out1  = base + OFF_OUT1;
    float* h2    = base + OFF_H2;
    float* asrc1 = base + OFF_ASRC1;
    float* adst1 = base + OFF_ADST1;
    float* asrc2 = base + OFF_ASRC2;
    float* adst2 = base + OFF_ADST2;
    float* pool  = base + OFF_POOL;
    float* cnt   = base + OFF_CNT;
    int* deg     = (int*)(base + OFF_DEG);
    int* rowptr  = (int*)(base + OFF_ROWPTR);
    int* wofs    = (int*)(base + OFF_WOFS);
    int* bsum    = (int*)(base + OFF_BSUM);
    int* col     = (int*)(base + OFF_COL);

    // one-time side stream + events (created on first, non-captured call)
    static cudaStream_t s2 = nullptr;
    static cudaEvent_t evFork = nullptr, evJoin = nullptr;
    if (s2 == nullptr) {
        cudaStreamCreateWithFlags(&s2, cudaStreamNonBlocking);
        cudaEventCreateWithFlags(&evFork, cudaEventDisableTiming);
        cudaEventCreateWithFlags(&evJoin, cudaEventDisableTiming);
    }

    // --- fork: CSR build + pool zero + counts on s2 -------------------------
    cudaEventRecord(evFork, 0);
    cudaStreamWaitEvent(s2, evFork, 0);

    fill_f32<<<(unsigned)((ZERO_CNT + 255) / 256), 256, 0, s2>>>(pool, ZERO_CNT);
    fill_i32<<<(n + 255) / 256, 256, 0, s2>>>(deg, n, 1);       // self loop
    deg_kernel<<<(e + 511) / 512, 512, 0, s2>>>(edst, e, deg);
    scan1_kernel<<<nb, 1024, 0, s2>>>(deg, wofs, bsum, n);      // partials in wofs
    scan2_kernel<<<1, 1024, 0, s2>>>(bsum, nb);
    scan3_kernel<<<nb, 1024, 0, s2>>>(deg, wofs, bsum, rowptr, wofs, n);
    scatter_kernel<<<(et + 511) / 512, 512, 0, s2>>>(esrc, edst, e, et, wofs, col);
    count_kernel<<<(n + 255) / 256, 256, 0, s2>>>(bat, n, cnt);

    cudaEventRecord(evJoin, s2);

    // --- main stream: GEMM1 (3xTF32 tensor core) + attscore1 ------------------
    {
        dim3 grid(HC1 / 128, (n + 127) / 128);
        mma_gemm_kernel<<<grid, 256>>>(x, W1, h1, n, HC1, F_IN);
    }
    attscore_kernel<H1_, C1_><<<(n * 32 + 255) / 256, 256>>>(h1, as1, ad1, asrc1, adst1, n);

    // --- join, then fused layer 1 (warp-per-node) ----------------------------
    cudaStreamWaitEvent(0, evJoin, 0);
    gat_warp_kernel<H1_, C1_, false><<<(n + 7) / 8, 256>>>(
        rowptr, col, h1, asrc1, adst1, b1, out1, nullptr, nullptr, n);

    // --- layer 2 -------------------------------------------------------------
    {
        dim3 grid(C2_ / 128, (n + 127) / 128);
        mma_gemm_kernel<<<grid, 256>>>(out1, W2, h2, n, C2_, HC1);
    }
    attscore_kernel<1, C2_><<<(n * 32 + 255) / 256, 256>>>(h2, as2, ad2, asrc2, adst2, n);
    gat_warp_kernel<1, C2_, true><<<(n + 7) / 8, 256>>>(
        rowptr, col, h2, asrc2, adst2, b2, nullptr, bat, pool, n);

    // --- head ----------------------------------------------------------------
    final_kernel<<<1, NG * NCLS>>>(pool, cnt, lw, lb, out);
}

// round 15
// speedup vs baseline: 1.3797x; 1.0118x over previous
#include <cuda_runtime.h>
#include <cuda_bf16.h>
#include <math.h>
#include <stdint.h>

// ---------------------------------------------------------------------------
// Problem constants
// ---------------------------------------------------------------------------
#define NV    50000      // nodes
#define NE    800000     // edges (before self loops)
#define ET    (NE + NV)  // edges + self loops
#define F_IN  128
#define H1_   4
#define C1_   64
#define HC1   256        // H1*C1
#define C2_   128
#define NG    32         // graphs
#define NCLS  5

// ---------------------------------------------------------------------------
// Scratch (floats + ints in one __device__ buffer)
// ---------------------------------------------------------------------------
static const size_t OFF_H1    = 0;
static const size_t OFF_OUT1  = OFF_H1   + (size_t)NV * HC1;
static const size_t OFF_H2    = OFF_OUT1 + (size_t)NV * HC1;
static const size_t OFF_ASRC1 = OFF_H2   + (size_t)NV * C2_;
static const size_t OFF_ADST1 = OFF_ASRC1 + (size_t)NV * H1_;
static const size_t OFF_ASRC2 = OFF_ADST1 + (size_t)NV * H1_;
static const size_t OFF_ADST2 = OFF_ASRC2 + (size_t)NV;
static const size_t ATT_FILL  = (size_t)NV * (H1_ * 2 + 2);     // asrc1..adst2
static const size_t OFF_POOL  = OFF_ADST2 + (size_t)NV;          // zero region start
static const size_t OFF_CNT   = OFF_POOL + (size_t)NG * C2_;
static const size_t ZERO_CNT  = OFF_CNT + NG - OFF_POOL;
// int region
static const size_t OFF_DEG    = OFF_CNT + NG;
static const size_t OFF_ROWPTR = OFF_DEG + NV;
static const size_t OFF_WOFS   = OFF_ROWPTR + NV + 1;   // also scan partials
static const size_t OFF_BSUM   = OFF_WOFS + NV;
static const size_t OFF_COL    = OFF_BSUM + 1024;
static const size_t TOTAL_F    = OFF_COL + ET;

__device__ __align__(128) float g_scratch[TOTAL_F];

// ---------------------------------------------------------------------------
// helpers
// ---------------------------------------------------------------------------
__device__ __forceinline__ void red_add_v4(float* addr, float4 v) {
    asm volatile("red.global.add.v4.f32 [%0], {%1, %2, %3, %4};"
                 :: "l"(addr), "f"(v.x), "f"(v.y), "f"(v.z), "f"(v.w)
                 : "memory");
}

// ---------------------------------------------------------------------------
// mma.sync tf32 GEMM with 3xTF32 error compensation (~fp32 accuracy).
// C[M,Ntot] = A[M,K] @ B[K,Ntot]; 128x128 block, BK=32, 8 warps of 64x32.
// Fused attention-score epilogue: asrc[row,h] += sum_c C[row,c]*att_s[c],
// adst likewise (atomic partial per block; asrc/adst pre-zeroed).
// ---------------------------------------------------------------------------
__device__ __forceinline__ void mma_tf32(float* c, const uint32_t* a,
                                         const uint32_t* b) {
    asm volatile(
        "mma.sync.aligned.m16n8k8.row.col.f32.tf32.tf32.f32 "
        "{%0,%1,%2,%3}, {%4,%5,%6,%7}, {%8,%9}, {%0,%1,%2,%3};"
        : "+f"(c[0]), "+f"(c[1]), "+f"(c[2]), "+f"(c[3])
        : "r"(a[0]), "r"(a[1]), "r"(a[2]), "r"(a[3]), "r"(b[0]), "r"(b[1]));
}

__device__ __forceinline__ void tf32_split(float x, uint32_t& hi, uint32_t& lo) {
    uint32_t h;
    asm("cvt.rna.tf32.f32 %0, %1;" : "=r"(h) : "f"(x));
    float r = x - __uint_as_float(h);
    uint32_t l;
    asm("cvt.rna.tf32.f32 %0, %1;" : "=r"(l) : "f"(r));
    hi = h; lo = l;
}

#define SPAD 36   // smem row stride in floats: bank = (4*row + col) % 32

__global__ __launch_bounds__(256, 1)
void mma_gemm_kernel(const float* __restrict__ A, const float* __restrict__ B,
                     float* __restrict__ C, int M, int Ntot, int K,
                     const float* __restrict__ att_s,
                     const float* __restrict__ att_d,
                     float* __restrict__ asrc, float* __restrict__ adst,
                     int Hatt, int Catt) {
    __shared__ float As[128 * SPAD];   // As[r][k]  (M-row major, 32 k)
    __shared__ float Bs[128 * SPAD];   // Bs[n][k]  (transposed B tile)
    const int tid  = threadIdx.x;
    const int wid  = tid >> 5, lane = tid & 31;
    const int g    = lane >> 2, tig = lane & 3;
    const int wm   = wid >> 2, wn = wid & 3;     // warp tile (wm*64, wn*32)
    const int m_base = blockIdx.y << 7;
    const int n0     = blockIdx.x << 7;

    float c[4][4][4];
#pragma unroll
    for (int mi = 0; mi < 4; mi++)
#pragma unroll
        for (int ni = 0; ni < 4; ni++)
#pragma unroll
            for (int r = 0; r < 4; r++) c[mi][ni][r] = 0.f;

    for (int k0 = 0; k0 < K; k0 += 32) {
        // stage A tile 128x32 (float4, coalesced)
#pragma unroll
        for (int i = 0; i < 4; i++) {
            int t = tid + i * 256;
            int r = t >> 3, cc = (t & 7) << 2;
            int gr = m_base + r;
            float4 v = make_float4(0.f, 0.f, 0.f, 0.f);
            if (gr < M) v = *(const float4*)(A + (size_t)gr * K + k0 + cc);
            *(float4*)(As + r * SPAD + cc) = v;
        }
        // stage B tile transposed: Bs[n][k]
#pragma unroll
        for (int i = 0; i < 4; i++) {
            int t = tid + i * 256;
            int nn = t & 127, kb = (t >> 7) << 2;
            const float* bp = B + (size_t)(k0 + kb) * Ntot + n0 + nn;
            float4 v;
            v.x = bp[0];
            v.y = bp[(size_t)Ntot];
            v.z = bp[(size_t)Ntot * 2];
            v.w = bp[(size_t)Ntot * 3];
            *(float4*)(Bs + nn * SPAD + kb) = v;
        }
        __syncthreads();

#pragma unroll
        for (int ks = 0; ks < 32; ks += 8) {
            uint32_t ah[4][4], al[4][4];
#pragma unroll
            for (int mi = 0; mi < 4; mi++) {
                int r0 = wm * 64 + mi * 16 + g;
                const float* ap = As + ks + tig;
                tf32_split(ap[r0 * SPAD],           ah[mi][0], al[mi][0]);
                tf32_split(ap[(r0 + 8) * SPAD],     ah[mi][1], al[mi][1]);
                tf32_split(ap[r0 * SPAD + 4],       ah[mi][2], al[mi][2]);
                tf32_split(ap[(r0 + 8) * SPAD + 4], ah[mi][3], al[mi][3]);
            }
            uint32_t bh[4][2], bl[4][2];
#pragma unroll
            for (int ni = 0; ni < 4; ni++) {
                const float* bp = Bs + (wn * 32 + ni * 8 + g) * SPAD + ks;
                tf32_split(bp[tig],     bh[ni][0], bl[ni][0]);
                tf32_split(bp[tig + 4], bh[ni][1], bl[ni][1]);
            }
#pragma unroll
            for (int mi = 0; mi < 4; mi++)
#pragma unroll
                for (int ni = 0; ni < 4; ni++) {
                    mma_tf32(c[mi][ni], al[mi], bh[ni]);
                    mma_tf32(c[mi][ni], ah[mi], bl[ni]);
                    mma_tf32(c[mi][ni], ah[mi], bh[ni]);
                }
        }
        __syncthreads();
    }

    // epilogue: store C; c0 (g, 2t), c1 (g, 2t+1), c2 (g+8, 2t), c3 (g+8, 2t+1)
#pragma unroll
    for (int mi = 0; mi < 4; mi++) {
        int r0 = m_base + wm * 64 + mi * 16 + g;
#pragma unroll
        for (int ni = 0; ni < 4; ni++) {
            int col = n0 + wn * 32 + ni * 8 + tig * 2;
            if (r0 < M)
                *(float2*)(C + (size_t)r0 * Ntot + col) =
                    make_float2(c[mi][ni][0], c[mi][ni][1]);
            if (r0 + 8 < M)
                *(float2*)(C + (size_t)(r0 + 8) * Ntot + col) =
                    make_float2(c[mi][ni][2], c[mi][ni][3]);
        }
    }

    // fused attention-score partials. A thread's cols all lie in one head
    // (32-col warp window, Catt >= 64).
    if (att_s != nullptr) {
        const int head = (n0 + wn * 32) / Catt;
#pragma unroll
        for (int mi = 0; mi < 4; mi++) {
#pragma unroll
            for (int rh = 0; rh < 2; rh++) {
                int row = m_base + wm * 64 + mi * 16 + g + rh * 8;
                float ss = 0.f, sd = 0.f;
#pragma unroll
                for (int ni = 0; ni < 4; ni++) {
#pragma unroll
                    for (int p = 0; p < 2; p++) {
                        int col = n0 + wn * 32 + ni * 8 + tig * 2 + p;
                        float cv = c[mi][ni][rh * 2 + p];
                        ss += cv * __ldg(att_s + col);
                        sd += cv * __ldg(att_d + col);
                    }
                }
                // reduce across the 4 tig lanes sharing this row
                ss += __shfl_down_sync(0xffffffffu, ss, 1, 4);
                ss += __shfl_down_sync(0xffffffffu, ss, 2, 4);
                sd += __shfl_down_sync(0xffffffffu, sd, 1, 4);
                sd += __shfl_down_sync(0xffffffffu, sd, 2, 4);
                if (tig == 0 && row < M) {
                    atomicAdd(&asrc[row * Hatt + head], ss);
                    atomicAdd(&adst[row * Hatt + head], sd);
                }
            }
        }
    }
}

// ---------------------------------------------------------------------------
// fills
// ---------------------------------------------------------------------------
__global__ void fill_f32(float* p, size_t n) {
    size_t i = (size_t)blockIdx.x * blockDim.x + threadIdx.x;
    if (i < n) p[i] = 0.0f;
}
__global__ void fill_i32(int* p, size_t n, int v) {
    size_t i = (size_t)blockIdx.x * blockDim.x + threadIdx.x;
    if (i < n) p[i] = v;
}

// ---------------------------------------------------------------------------
// CSR build
// ---------------------------------------------------------------------------
__global__ void deg_kernel(const int* __restrict__ edst, int e, int* deg) {
    int i = blockIdx.x * blockDim.x + threadIdx.x;
    if (i < e) atomicAdd(&deg[edst[i]], 1);
}

__device__ __forceinline__ int block_scan_1024(int v, int* wsum) {
    int lane = threadIdx.x & 31, wid = threadIdx.x >> 5;
    int x = v;
#pragma unroll
    for (int o = 1; o < 32; o <<= 1) {
        int t = __shfl_up_sync(0xffffffffu, x, o);
        if (lane >= o) x += t;
    }
    if (lane == 31) wsum[wid] = x;
    __syncthreads();
    if (wid == 0) {
        int w = wsum[lane];
#pragma unroll
        for (int o = 1; o < 32; o <<= 1) {
            int t = __shfl_up_sync(0xffffffffu, w, o);
            if (lane >= o) w += t;
        }
        wsum[lane] = w;
    }
    __syncthreads();
    if (wid > 0) x += wsum[wid - 1];
    return x;
}

__global__ void scan1_kernel(const int* __restrict__ deg, int* partial,
                             int* bsums, int n) {
    __shared__ int wsum[32];
    int i = blockIdx.x * 1024 + threadIdx.x;
    int v = (i < n) ? deg[i] : 0;
    int x = block_scan_1024(v, wsum);
    if (i < n) partial[i] = x;
    if (threadIdx.x == 1023) bsums[blockIdx.x] = x;
}

__global__ void scan2_kernel(int* bsums, int nb) {
    __shared__ int wsum[32];
    int v = (threadIdx.x < nb) ? bsums[threadIdx.x] : 0;
    int x = block_scan_1024(v, wsum);
    if (threadIdx.x < nb) bsums[threadIdx.x] = x;
}

__global__ void scan3_kernel(const int* __restrict__ deg,
                             int* __restrict__ partial,
                             const int* __restrict__ bscan,
                             int* __restrict__ rowptr,
                             int* __restrict__ wofs, int n) {
    int i = blockIdx.x * 1024 + threadIdx.x;
    if (i >= n) return;
    int off = blockIdx.x > 0 ? bscan[blockIdx.x - 1] : 0;
    int inc = partial[i] + off;
    rowptr[i + 1] = inc;
    wofs[i] = inc - deg[i];
    if (i == 0) rowptr[0] = 0;
}

__global__ void scatter_kernel(const int* __restrict__ esrc,
                               const int* __restrict__ edst, int e, int et,
                               int* wofs, int* col) {
    int i = blockIdx.x * blockDim.x + threadIdx.x;
    if (i >= et) return;
    int s, d;
    if (i < e) { s = esrc[i]; d = edst[i]; }
    else       { s = d = i - e; }
    int pos = atomicAdd(&wofs[d], 1);
    col[pos] = s;
}

// ---------------------------------------------------------------------------
// warp-per-node fused GAT layer. No block barriers: per-warp smem staging,
// register den with one final warp reduction (unnormalized-weight trick).
// blockDim = 256 (8 warps = 8 nodes per block).
// ---------------------------------------------------------------------------
template<int H, int C, bool POOL>
__global__ __launch_bounds__(256)
void gat_warp_kernel(const int* __restrict__ rowptr,
                     const int* __restrict__ colidx,
                     const float* __restrict__ h,
                     const float* __restrict__ asrc,
                     const float* __restrict__ adst,
                     const float* __restrict__ bias,
                     float* __restrict__ out,
                     const int* __restrict__ batch,
                     float* __restrict__ pool, int n) {
    constexpr int HC  = H * C;
    constexpr int PER = HC / 32;   // floats per lane (8 for L1, 4 for L2)
    constexpr int NF4 = PER / 4;   // float4s per lane (2 or 1)
    const int wid  = threadIdx.x >> 5;
    const int lane = threadIdx.x & 31;
    const int node = blockIdx.x * 8 + wid;

    __shared__ float ssw[8][32 * H];
    __shared__ int   ssx[8][32];

    if (node >= n) return;

    const int row0 = rowptr[node];
    const int deg  = rowptr[node + 1] - row0;
    const int myh  = (lane * PER) / C;

    float ad[H], den[H];
#pragma unroll
    for (int hh = 0; hh < H; hh++) {
        ad[hh]  = adst[node * H + hh];
        den[hh] = 0.f;
    }
    float4 acc[NF4];
#pragma unroll
    for (int q = 0; q < NF4; q++) acc[q] = make_float4(0.f, 0.f, 0.f, 0.f);

    for (int base = 0; base < deg; base += 32) {
        int m = min(32, deg - base);
        if (lane < m) {
            int s = colidx[row0 + base + lane];
            ssx[wid][lane] = s;
#pragma unroll
            for (int hh = 0; hh < H; hh++) {
                float a = asrc[s * H + hh] + ad[hh];
                a = a > 0.f ? a : 0.2f * a;
                float w = __expf(a);
                ssw[wid][lane * H + hh] = w;
                den[hh] += w;
            }
        }
        __syncwarp();
#pragma unroll 4
        for (int j = 0; j < m; j++) {
            float w = ssw[wid][j * H + myh];
            const float4* hp =
                (const float4*)(h + (size_t)ssx[wid][j] * HC + lane * PER);
#pragma unroll
            for (int q = 0; q < NF4; q++) {
                float4 hv = hp[q];
                acc[q].x = fmaf(w, hv.x, acc[q].x);
                acc[q].y = fmaf(w, hv.y, acc[q].y);
                acc[q].z = fmaf(w, hv.z, acc[q].z);
                acc[q].w = fmaf(w, hv.w, acc[q].w);
            }
        }
        __syncwarp();
    }

    // reduce den across lanes (all lanes get the sums)
#pragma unroll
    for (int hh = 0; hh < H; hh++)
#pragma unroll
        for (int o = 16; o; o >>= 1)
            den[hh] += __shfl_xor_sync(0xffffffffu, den[hh], o);

    const float rden = 1.0f / (den[myh] + 1e-16f);
#pragma unroll
    for (int q = 0; q < NF4; q++) {
        int c0 = lane * PER + q * 4;
        float4 bv = *(const float4*)(bias + c0);
        float4 v;
        v.x = acc[q].x * rden + bv.x;
        v.y = acc[q].y * rden + bv.y;
        v.z = acc[q].z * rden + bv.z;
        v.w = acc[q].w * rden + bv.w;
        v.x = v.x > 0.f ? v.x : expm1f(v.x);
        v.y = v.y > 0.f ? v.y : expm1f(v.y);
        v.z = v.z > 0.f ? v.z : expm1f(v.z);
        v.w = v.w > 0.f ? v.w : expm1f(v.w);
        if (POOL) {
            red_add_v4(pool + (size_t)batch[node] * HC + c0, v);
        } else {
            *(float4*)(out + (size_t)node * HC + c0) = v;
        }
    }
}

// ---------------------------------------------------------------------------
// graph-size counts + linear head
// ---------------------------------------------------------------------------
__global__ void count_kernel(const int* __restrict__ batch, int n,
                             float* __restrict__ cnt) {
    __shared__ int sc[NG];
    if (threadIdx.x < NG) sc[threadIdx.x] = 0;
    __syncthreads();
    int i = blockIdx.x * blockDim.x + threadIdx.x;
    if (i < n) atomicAdd(&sc[batch[i]], 1);
    __syncthreads();
    if (threadIdx.x < NG && sc[threadIdx.x])
        atomicAdd(&cnt[threadIdx.x], (float)sc[threadIdx.x]);
}

__global__ void final_kernel(const float* __restrict__ pool,
                             const float* __restrict__ cnt,
                             const float* __restrict__ w,
                             const float* __restrict__ b,
                             float* __restrict__ out) {
    int t = threadIdx.x;
    if (t >= NG * NCLS) return;
    int g = t / NCLS, k = t % NCLS;
    float s = 0.f;
#pragma unroll 8
    for (int c = 0; c < C2_; c++) s += pool[g * C2_ + c] * w[c * NCLS + k];
    float n = cnt[g];
    out[t] = s / (n > 1.f ? n : 1.f) + b[k];
}

// ---------------------------------------------------------------------------
// launch
// ---------------------------------------------------------------------------
extern "C" void kernel_launch(void* const* d_in, const int* in_sizes, int n_in,
                              void* d_out, int out_size) {
    const float* x   = (const float*)d_in[0];
    const int*   ei  = (const int*)d_in[1];   // int32 (JAX x64 disabled)
    const int*   bat = (const int*)d_in[2];
    const float* W1  = (const float*)d_in[3];
    const float* as1 = (const float*)d_in[4];
    const float* ad1 = (const float*)d_in[5];
    const float* b1  = (const float*)d_in[6];
    const float* W2  = (const float*)d_in[7];
    const float* as2 = (const float*)d_in[8];
    const float* ad2 = (const float*)d_in[9];
    const float* b2  = (const float*)d_in[10];
    const float* lw  = (const float*)d_in[11];
    const float* lb  = (const float*)d_in[12];
    float* out = (float*)d_out;

    const int n  = in_sizes[0] / F_IN;   // 50000
    const int e  = in_sizes[1] / 2;      // 800000
    const int et = e + n;
    const int nb = (n + 1023) / 1024;    // scan blocks
    const int* esrc = ei;
    const int* edst = ei + e;

    float* base;
    cudaGetSymbolAddress((void**)&base, g_scratch);
    float* h1    = base + OFF_H1;
    float* out1  = base + OFF_OUT1;
    float* h2    = base + OFF_H2;
    float* asrc1 = base + OFF_ASRC1;
    float* adst1 = base + OFF_ADST1;
    float* asrc2 = base + OFF_ASRC2;
    float* adst2 = base + OFF_ADST2;
    float* pool  = base + OFF_POOL;
    float* cnt   = base + OFF_CNT;
    int* deg     = (int*)(base + OFF_DEG);
    int* rowptr  = (int*)(base + OFF_ROWPTR);
    int* wofs    = (int*)(base + OFF_WOFS);
    int* bsum    = (int*)(base + OFF_BSUM);
    int* col     = (int*)(base + OFF_COL);

    // one-time side stream + events (created on first, non-captured call)
    static cudaStream_t s2 = nullptr;
    static cudaEvent_t evFork = nullptr, evJoin = nullptr;
    if (s2 == nullptr) {
        cudaStreamCreateWithFlags(&s2, cudaStreamNonBlocking);
        cudaEventCreateWithFlags(&evFork, cudaEventDisableTiming);
        cudaEventCreateWithFlags(&evJoin, cudaEventDisableTiming);
    }

    // --- fork: CSR build + pool zero + counts on s2 -------------------------
    cudaEventRecord(evFork, 0);
    cudaStreamWaitEvent(s2, evFork, 0);

    fill_f32<<<(unsigned)((ZERO_CNT + 255) / 256), 256, 0, s2>>>(pool, ZERO_CNT);
    fill_i32<<<(n + 255) / 256, 256, 0, s2>>>(deg, n, 1);       // self loop
    deg_kernel<<<(e + 511) / 512, 512, 0, s2>>>(edst, e, deg);
    scan1_kernel<<<nb, 1024, 0, s2>>>(deg, wofs, bsum, n);      // partials in wofs
    scan2_kernel<<<1, 1024, 0, s2>>>(bsum, nb);
    scan3_kernel<<<nb, 1024, 0, s2>>>(deg, wofs, bsum, rowptr, wofs, n);
    scatter_kernel<<<(et + 511) / 512, 512, 0, s2>>>(esrc, edst, e, et, wofs, col);
    count_kernel<<<(n + 255) / 256, 256, 0, s2>>>(bat, n, cnt);

    cudaEventRecord(evJoin, s2);

    // --- main stream: zero att buffers, then GEMM1 + fused attscore1 ---------
    fill_f32<<<(unsigned)((ATT_FILL + 255) / 256), 256>>>(asrc1, ATT_FILL);
    {
        dim3 grid(HC1 / 128, (n + 127) / 128);
        mma_gemm_kernel<<<grid, 256>>>(x, W1, h1, n, HC1, F_IN,
                                       as1, ad1, asrc1, adst1, H1_, C1_);
    }

    // --- join, then fused layer 1 (warp-per-node) ----------------------------
    cudaStreamWaitEvent(0, evJoin, 0);
    gat_warp_kernel<H1_, C1_, false><<<(n + 7) / 8, 256>>>(
        rowptr, col, h1, asrc1, adst1, b1, out1, nullptr, nullptr, n);

    // --- layer 2 (GEMM2 + fused attscore2) ------------------------------------
    {
        dim3 grid(C2_ / 128, (n + 127) / 128);
        mma_gemm_kernel<<<grid, 256>>>(out1, W2, h2, n, C2_, HC1,
                                       as2, ad2, asrc2, adst2, 1, C2_);
    }
    gat_warp_kernel<1, C2_, true><<<(n + 7) / 8, 256>>>(
        rowptr, col, h2, asrc2, adst2, b2, nullptr, bat, pool, n);

    // --- head ----------------------------------------------------------------
    final_kernel<<<1, NG * NCLS>>>(pool, cnt, lw, lb, out);
}